// round 9
// baseline (speedup 1.0000x reference)
#include <cuda_runtime.h>
#include <math.h>

#define SEQ   40
#define H     4096
#define OUT   128
#define NBLK  128
#define NTHR  512
#define JPB   32                  // hidden indices per block
#define RPB   128                 // rows per block (4 gates x 32)
#define ROWS  (4 * H)
#define CH_B  32768               // bytes per chunk (128 rows x 256 cols)
#define NCHUNK 16
#define RCH   3                   // chunks 0..2 in registers (48 regs/thread)
#define SCH   6                   // chunks 3..8 in smem (192 KB)
#define BLOCK_WQ (RPB * H)        // 512 KB s8 weights per block
#define SMEM_W (SCH * CH_B)       // 196608

// ---- persistent device state (no allocations allowed) ----
__device__ float    g_h[H];                                      // fp32 h_last for dense
__device__ unsigned g_hq[2][H / 2];                              // ping-pong s16x2 h
__device__ float    g_scale[ROWS];                               // per-row dequant scale
__device__ __align__(256) unsigned char g_wq[(size_t)NBLK * BLOCK_WQ]; // 67MB s8
__device__ __align__(16) unsigned g_stamp[NBLK];                 // per-block step stamps

// ---------------- single-pass quant; layout [B][chunk][warp][k][lane][16B] ----------------
// Within a lane's 16B unit k: u32 {row 2k w0, row 2k w1, row 2k+1 w0, row 2k+1 w1},
// w0 = cols 8l..8l+3, w1 = cols 8l+4..8l+7 of chunk-local 256 cols.
__global__ __launch_bounds__(256) void quant_kernel(const float* __restrict__ w_hh) {
    __shared__ float wmax[8];
    const int r    = blockIdx.x;             // gate row (gate*H + j)
    const int tid  = threadIdx.x;
    const int lane = tid & 31, wrp = tid >> 5;

    const float4* rp = (const float4*)(w_hh + (size_t)r * H) + tid * 4;
    const float4 vs[4] = {__ldg(rp), __ldg(rp + 1), __ldg(rp + 2), __ldg(rp + 3)};

    float m = 0.0f;
    #pragma unroll
    for (int q = 0; q < 4; ++q)
        m = fmaxf(m, fmaxf(fmaxf(fabsf(vs[q].x), fabsf(vs[q].y)),
                           fmaxf(fabsf(vs[q].z), fabsf(vs[q].w))));
    #pragma unroll
    for (int o = 16; o > 0; o >>= 1) m = fmaxf(m, __shfl_xor_sync(0xffffffffu, m, o));
    if (lane == 0) wmax[wrp] = m;
    __syncthreads();
    float mx = wmax[0];
    #pragma unroll
    for (int w = 1; w < 8; ++w) mx = fmaxf(mx, wmax[w]);
    if (tid == 0) g_scale[r] = mx * (1.0f / 127.0f);
    const float inv = (mx > 0.0f) ? 127.0f / mx : 0.0f;

    unsigned b[16];
    #pragma unroll
    for (int q = 0; q < 4; ++q) {
        b[4 * q + 0] = __float_as_uint(fmaf(vs[q].x, inv, 8388736.0f));
        b[4 * q + 1] = __float_as_uint(fmaf(vs[q].y, inv, 8388736.0f));
        b[4 * q + 2] = __float_as_uint(fmaf(vs[q].z, inv, 8388736.0f));
        b[4 * q + 3] = __float_as_uint(fmaf(vs[q].w, inv, 8388736.0f));
    }
    uint4 o;
    #pragma unroll
    for (int q = 0; q < 4; ++q) {
        unsigned t0 = __byte_perm(b[4 * q + 0], b[4 * q + 1], 0x0040);
        unsigned t1 = __byte_perm(b[4 * q + 2], b[4 * q + 3], 0x0040);
        ((unsigned*)&o)[q] = __byte_perm(t0, t1, 0x5410) ^ 0x80808080u;
    }
    // thread covers cols 16tid..16tid+15 of row r
    const int j = r & (H - 1), gate = r >> 12;
    const int B = j >> 5;
    const int rloc = gate * 32 + (j & 31);
    const int w_ = rloc >> 3, r8 = rloc & 7, k = r8 >> 1, half = r8 & 1;
    const int chunk = tid >> 4;
    const int l0 = (tid & 15) * 2;          // first of two lanes covered
    unsigned char* dst = g_wq + (size_t)B * BLOCK_WQ + (size_t)chunk * CH_B
                       + w_ * 2048 + k * 512 + half * 8;
    *(uint2*)(dst + l0 * 16)       = make_uint2(o.x, o.y);   // lane l0: cols ..+0..7
    *(uint2*)(dst + (l0 + 1) * 16) = make_uint2(o.z, o.w);   // lane l0+1: cols +8..15
}

// one chunk of dp2a against h (hq smem) with weights from WEXPR(k)
#define DOCHUNK(cc, WEXPR) do {                                           \
    const uint4 hv = *(const uint4*)(hq + (cc) * 128 + 4 * lane);         \
    _Pragma("unroll")                                                     \
    for (int k = 0; k < 4; ++k) {                                         \
        const uint4 wv = (WEXPR);                                         \
        acc[2*k]   = __dp2a_lo((int)hv.x, (int)wv.x, acc[2*k]);           \
        acc[2*k]   = __dp2a_hi((int)hv.y, (int)wv.x, acc[2*k]);           \
        acc[2*k]   = __dp2a_lo((int)hv.z, (int)wv.y, acc[2*k]);           \
        acc[2*k]   = __dp2a_hi((int)hv.w, (int)wv.y, acc[2*k]);           \
        acc[2*k+1] = __dp2a_lo((int)hv.x, (int)wv.z, acc[2*k+1]);         \
        acc[2*k+1] = __dp2a_hi((int)hv.y, (int)wv.z, acc[2*k+1]);         \
        acc[2*k+1] = __dp2a_lo((int)hv.z, (int)wv.w, acc[2*k+1]);         \
        acc[2*k+1] = __dp2a_hi((int)hv.w, (int)wv.w, acc[2*k+1]);         \
    } } while (0)

#define SMW(cc, kk) (*(const uint4*)(wsm + (size_t)((cc) - RCH) * CH_B    \
                     + wid * 2048 + (kk) * 512 + lane * 16))

#define LDSB(dst, cc) do {                                                \
    const uint4* _p = (const uint4*)(wlane + (size_t)(cc) * CH_B);        \
    dst[0] = __ldg(_p); dst[1] = __ldg(_p + 32);                          \
    dst[2] = __ldg(_p + 64); dst[3] = __ldg(_p + 96); } while (0)

// ---------------- persistent LSTM kernel (weights resident in regs+smem) ----------------
__global__ __launch_bounds__(NTHR, 1)
void lstm_persistent_kernel(const float* __restrict__ x,
                            const float* __restrict__ w_ih,
                            const float* __restrict__ b_ih,
                            const float* __restrict__ b_hh,
                            const float* __restrict__ dense_w,
                            const float* __restrict__ dense_b,
                            float* __restrict__ out) {
    extern __shared__ unsigned char wsm[];       // 192 KB resident weights (chunks 3..8)
    __shared__ unsigned hq[H / 2];               // 8 KB packed h_{t-1}
    __shared__ float gsm[4][JPB];
    __shared__ float c_s[JPB];
    __shared__ float hnew[JPB];
    __shared__ float red[16];

    const int tid  = threadIdx.x;
    const int lane = tid & 31;
    const int wid  = tid >> 5;
    const int j0   = blockIdx.x * JPB;
    const unsigned char* wsrc  = g_wq + (size_t)blockIdx.x * BLOCK_WQ;
    const unsigned char* wlane = wsrc + wid * 2048 + lane * 16;

    // load register-resident chunks 0..2 (48 regs/thread)
    uint4 wr0[4], wr1[4], wr2[4];
    #pragma unroll
    for (int k = 0; k < 4; ++k) {
        wr0[k] = *(const uint4*)(wlane + 0 * CH_B + k * 512);
        wr1[k] = *(const uint4*)(wlane + 1 * CH_B + k * 512);
        wr2[k] = *(const uint4*)(wlane + 2 * CH_B + k * 512);
    }
    // copy smem-resident chunks 3..8 (192 KB, coalesced)
    {
        const uint4* gsrc = (const uint4*)(wsrc + RCH * CH_B);
        uint4* d = (uint4*)wsm;
        #pragma unroll
        for (int i = 0; i < SMEM_W / 16 / NTHR; ++i)
            d[tid + i * NTHR] = __ldg(gsrc + tid + i * NTHR);
    }

    const unsigned base = *(volatile unsigned*)&g_stamp[blockIdx.x];
    if (tid < JPB) c_s[tid] = 0.0f;

    for (int t = 0; t < SEQ; ++t) {
        if (t > 0) {
            // prefetch first two streamed chunks before the barrier (independent of h)
            uint4 sb0[4], sb1[4];
            LDSB(sb0, 9); LDSB(sb1, 10);

            // grid barrier: warp 0 polls all 128 stamps
            if (wid == 0) {
                const unsigned* sp = g_stamp + lane * 4;
                for (;;) {
                    unsigned s0, s1, s2, s3;
                    asm volatile("ld.volatile.global.v4.u32 {%0,%1,%2,%3}, [%4];"
                                 : "=r"(s0), "=r"(s1), "=r"(s2), "=r"(s3) : "l"(sp));
                    const bool ok = (s0 - base) >= (unsigned)t && (s1 - base) >= (unsigned)t
                                 && (s2 - base) >= (unsigned)t && (s3 - base) >= (unsigned)t;
                    if (__all_sync(0xffffffffu, ok)) break;
                }
                __threadfence();
            }
            __syncthreads();
            ((uint4*)hq)[tid] = ((const uint4*)g_hq[(t - 1) & 1])[tid];
            __syncthreads();

            int acc[8] = {0, 0, 0, 0, 0, 0, 0, 0};
            // register chunks
            DOCHUNK(0, wr0[k]);
            DOCHUNK(1, wr1[k]);
            DOCHUNK(2, wr2[k]);
            // smem chunks
            DOCHUNK(3, SMW(3, k)); DOCHUNK(4, SMW(4, k)); DOCHUNK(5, SMW(5, k));
            DOCHUNK(6, SMW(6, k)); DOCHUNK(7, SMW(7, k)); DOCHUNK(8, SMW(8, k));
            // streamed chunks 9..15, double-buffered
            DOCHUNK(9,  sb0[k]); LDSB(sb0, 11);
            DOCHUNK(10, sb1[k]); LDSB(sb1, 12);
            DOCHUNK(11, sb0[k]); LDSB(sb0, 13);
            DOCHUNK(12, sb1[k]); LDSB(sb1, 14);
            DOCHUNK(13, sb0[k]); LDSB(sb0, 15);
            DOCHUNK(14, sb1[k]);
            DOCHUNK(15, sb0[k]);

            // reduce 8 rows per warp
            #pragma unroll
            for (int rr = 0; rr < 8; ++rr) {
                float a = __int2float_rn(acc[rr]);
                #pragma unroll
                for (int o = 16; o > 0; o >>= 1)
                    a += __shfl_down_sync(0xffffffffu, a, o);
                if (lane == 0) {
                    const int rloc = wid * 8 + rr;
                    const int gate = rloc >> 5, jj = rloc & 31;
                    gsm[gate][jj] = a * (g_scale[gate * H + j0 + jj] * (1.0f / 32767.0f));
                }
            }
        }
        __syncthreads();

        if (tid < JPB) {
            const int   j  = j0 + tid;
            const float xt = x[t];
            float v[4];
            #pragma unroll
            for (int g = 0; g < 4; ++g) {
                const int row = g * H + j;
                const float dot = (t > 0) ? gsm[g][tid] : 0.0f;
                v[g] = fmaf(w_ih[row], xt, b_ih[row] + b_hh[row]) + dot;
            }
            const float ig = 1.0f / (1.0f + expf(-v[0]));
            const float fg = 1.0f / (1.0f + expf(-v[1]));
            const float gg = tanhf(v[2]);
            const float og = 1.0f / (1.0f + expf(-v[3]));
            const float c  = fg * c_s[tid] + ig * gg;
            c_s[tid] = c;
            const float h = og * tanhf(c);
            hnew[tid] = h;
            if (t == SEQ - 1) g_h[j] = h;
        }
        __syncthreads();
        if (tid < JPB / 2) {
            const int q0 = __float2int_rn(hnew[2 * tid]     * 32767.0f);
            const int q1 = __float2int_rn(hnew[2 * tid + 1] * 32767.0f);
            g_hq[t & 1][j0 / 2 + tid] = __byte_perm((unsigned)q0, (unsigned)q1, 0x5410);
        }
        __syncthreads();
        if (tid == 0) {
            __threadfence();
            *(volatile unsigned*)&g_stamp[blockIdx.x] = base + (unsigned)(t + 1);
        }
    }

    // final sync: all blocks published h_last
    if (wid == 0) {
        const unsigned* sp = g_stamp + lane * 4;
        for (;;) {
            unsigned s0, s1, s2, s3;
            asm volatile("ld.volatile.global.v4.u32 {%0,%1,%2,%3}, [%4];"
                         : "=r"(s0), "=r"(s1), "=r"(s2), "=r"(s3) : "l"(sp));
            const bool ok = (s0 - base) >= SEQ && (s1 - base) >= SEQ
                         && (s2 - base) >= SEQ && (s3 - base) >= SEQ;
            if (__all_sync(0xffffffffu, ok)) break;
        }
        __threadfence();
    }
    __syncthreads();

    // dense epilogue: block b computes out[b] (NBLK == OUT)
    {
        const float* hw = g_h;
        const float* wr = dense_w + (size_t)blockIdx.x * H;
        float acc = 0.0f;
        #pragma unroll
        for (int k = tid; k < H; k += NTHR)
            acc += wr[k] * hw[k];
        #pragma unroll
        for (int o = 16; o > 0; o >>= 1)
            acc += __shfl_down_sync(0xffffffffu, acc, o);
        if (lane == 0) red[wid] = acc;
        __syncthreads();
        if (tid == 0) {
            float s = 0.0f;
            #pragma unroll
            for (int w = 0; w < 16; ++w) s += red[w];
            out[blockIdx.x] = s + dense_b[blockIdx.x];
        }
    }
}

extern "C" void kernel_launch(void* const* d_in, const int* in_sizes, int n_in,
                              void* d_out, int out_size) {
    const float* x       = (const float*)d_in[0];
    const float* w_ih    = (const float*)d_in[1];
    const float* w_hh    = (const float*)d_in[2];
    const float* b_ih    = (const float*)d_in[3];
    const float* b_hh    = (const float*)d_in[4];
    const float* dense_w = (const float*)d_in[5];
    const float* dense_b = (const float*)d_in[6];

    cudaFuncSetAttribute(lstm_persistent_kernel,
                         cudaFuncAttributeMaxDynamicSharedMemorySize, SMEM_W);
    quant_kernel<<<ROWS, 256>>>(w_hh);
    lstm_persistent_kernel<<<NBLK, NTHR, SMEM_W>>>(x, w_ih, b_ih, b_hh,
                                                   dense_w, dense_b, (float*)d_out);
}

// round 10
// speedup vs baseline: 1.0039x; 1.0039x over previous
#include <cuda_runtime.h>
#include <math.h>

#define SEQ   40
#define H     4096
#define OUT   128
#define NBLK  128
#define NTHR  1024
#define JPB   32                  // hidden indices per block
#define RPB   128                 // rows per block (4 gates x 32)
#define ROWS  (4 * H)
#define CH_B  32768               // bytes per chunk (128 rows x 256 cols)
#define NCHUNK 16
#define SCH   6                   // chunks 0..5 resident in smem (192 KB)
#define BLOCK_WQ (RPB * H)        // 512 KB s8 weights per block
#define SMEM_W (SCH * CH_B)       // 196608

// ---- persistent device state (no allocations allowed) ----
__device__ float    g_h[H];                                      // fp32 h_last for dense
__device__ unsigned g_hq[2][H / 2];                              // ping-pong s16x2 h
__device__ float    g_scale[ROWS];                               // per-row dequant scale
__device__ __align__(256) unsigned char g_wq[(size_t)NBLK * BLOCK_WQ]; // 67MB s8
__device__ __align__(16) unsigned g_stamp[NBLK];                 // per-block step stamps

// ---------------- single-pass quant; layout [B][chunk][row 0..127][256B] ----------------
__global__ __launch_bounds__(256) void quant_kernel(const float* __restrict__ w_hh) {
    __shared__ float wmax[8];
    const int r    = blockIdx.x;             // gate row (gate*H + j)
    const int tid  = threadIdx.x;
    const int lane = tid & 31, wrp = tid >> 5;

    const float4* rp = (const float4*)(w_hh + (size_t)r * H) + tid * 4;
    const float4 vs[4] = {__ldg(rp), __ldg(rp + 1), __ldg(rp + 2), __ldg(rp + 3)};

    float m = 0.0f;
    #pragma unroll
    for (int q = 0; q < 4; ++q)
        m = fmaxf(m, fmaxf(fmaxf(fabsf(vs[q].x), fabsf(vs[q].y)),
                           fmaxf(fabsf(vs[q].z), fabsf(vs[q].w))));
    #pragma unroll
    for (int o = 16; o > 0; o >>= 1) m = fmaxf(m, __shfl_xor_sync(0xffffffffu, m, o));
    if (lane == 0) wmax[wrp] = m;
    __syncthreads();
    float mx = wmax[0];
    #pragma unroll
    for (int w = 1; w < 8; ++w) mx = fmaxf(mx, wmax[w]);
    if (tid == 0) g_scale[r] = mx * (1.0f / 127.0f);
    const float inv = (mx > 0.0f) ? 127.0f / mx : 0.0f;

    unsigned b[16];
    #pragma unroll
    for (int q = 0; q < 4; ++q) {
        b[4 * q + 0] = __float_as_uint(fmaf(vs[q].x, inv, 8388736.0f));
        b[4 * q + 1] = __float_as_uint(fmaf(vs[q].y, inv, 8388736.0f));
        b[4 * q + 2] = __float_as_uint(fmaf(vs[q].z, inv, 8388736.0f));
        b[4 * q + 3] = __float_as_uint(fmaf(vs[q].w, inv, 8388736.0f));
    }
    uint4 o;
    #pragma unroll
    for (int q = 0; q < 4; ++q) {
        unsigned t0 = __byte_perm(b[4 * q + 0], b[4 * q + 1], 0x0040);
        unsigned t1 = __byte_perm(b[4 * q + 2], b[4 * q + 3], 0x0040);
        ((unsigned*)&o)[q] = __byte_perm(t0, t1, 0x5410) ^ 0x80808080u;
    }
    // thread covers cols 16tid..16tid+15 of row r
    const int j = r & (H - 1), gate = r >> 12;
    const int B = j >> 5;
    const int rloc = gate * 32 + (j & 31);
    *(uint4*)(g_wq + (size_t)B * BLOCK_WQ + (size_t)(tid >> 4) * CH_B
              + rloc * 256 + (tid & 15) * 16) = o;
}

// one chunk: 4 rows/warp, 8 cols/lane; wv row rr is a uint2
#define DOROW(rr, WV) do {                                                \
    acc[rr] = __dp2a_lo((int)hv.x, (int)(WV).x, acc[rr]);                 \
    acc[rr] = __dp2a_hi((int)hv.y, (int)(WV).x, acc[rr]);                 \
    acc[rr] = __dp2a_lo((int)hv.z, (int)(WV).y, acc[rr]);                 \
    acc[rr] = __dp2a_hi((int)hv.w, (int)(WV).y, acc[rr]);                 \
} while (0)

#define DOCHUNK_SM(cc) do {                                               \
    const uint4 hv = *(const uint4*)(hq + (cc) * 128 + 4 * lane);         \
    const unsigned char* _c = wsm + (size_t)(cc) * CH_B + wid * 1024 + lane * 8; \
    DOROW(0, *(const uint2*)(_c));                                        \
    DOROW(1, *(const uint2*)(_c + 256));                                  \
    DOROW(2, *(const uint2*)(_c + 512));                                  \
    DOROW(3, *(const uint2*)(_c + 768));                                  \
} while (0)

#define DOCHUNK_SB(cc, SB) do {                                           \
    const uint4 hv = *(const uint4*)(hq + (cc) * 128 + 4 * lane);         \
    DOROW(0, SB[0]); DOROW(1, SB[1]); DOROW(2, SB[2]); DOROW(3, SB[3]);   \
} while (0)

#define LDSB(dst, cc) do {                                                \
    const unsigned char* _p = wsrc + (size_t)(cc) * CH_B + wid * 1024 + lane * 8; \
    dst[0] = __ldg((const uint2*)(_p));                                   \
    dst[1] = __ldg((const uint2*)(_p + 256));                             \
    dst[2] = __ldg((const uint2*)(_p + 512));                             \
    dst[3] = __ldg((const uint2*)(_p + 768)); } while (0)

// ---------------- persistent LSTM kernel ----------------
__global__ __launch_bounds__(NTHR, 1)
void lstm_persistent_kernel(const float* __restrict__ x,
                            const float* __restrict__ w_ih,
                            const float* __restrict__ b_ih,
                            const float* __restrict__ b_hh,
                            const float* __restrict__ dense_w,
                            const float* __restrict__ dense_b,
                            float* __restrict__ out) {
    extern __shared__ unsigned char wsm[];       // 192 KB resident weights (chunks 0..5)
    __shared__ unsigned hq[H / 2];               // 8 KB packed h_{t-1}
    __shared__ float gsm[4][JPB];
    __shared__ float c_s[JPB];
    __shared__ float hnew[JPB];
    __shared__ float red[NTHR / 32];

    const int tid  = threadIdx.x;
    const int lane = tid & 31;
    const int wid  = tid >> 5;                   // 0..31; warp owns rows 4wid..4wid+3
    const int j0   = blockIdx.x * JPB;
    const unsigned char* wsrc = g_wq + (size_t)blockIdx.x * BLOCK_WQ;

    // copy smem-resident chunks 0..5 (192 KB, coalesced)
    {
        const uint4* gsrc = (const uint4*)wsrc;
        uint4* d = (uint4*)wsm;
        #pragma unroll
        for (int i = 0; i < SMEM_W / 16 / NTHR; ++i)
            d[tid + i * NTHR] = __ldg(gsrc + tid + i * NTHR);
    }

    const unsigned base = *(volatile unsigned*)&g_stamp[blockIdx.x];
    if (tid < JPB) c_s[tid] = 0.0f;

    for (int t = 0; t < SEQ; ++t) {
        if (t > 0) {
            // prefetch first three streamed chunks before the barrier
            uint2 sb0[4], sb1[4], sb2[4];
            LDSB(sb0, 6); LDSB(sb1, 7); LDSB(sb2, 8);

            // grid barrier: warp 0 polls all 128 stamps (4 per lane, one v4 load)
            if (wid == 0) {
                const unsigned* sp = g_stamp + lane * 4;
                for (;;) {
                    unsigned s0, s1, s2, s3;
                    asm volatile("ld.volatile.global.v4.u32 {%0,%1,%2,%3}, [%4];"
                                 : "=r"(s0), "=r"(s1), "=r"(s2), "=r"(s3) : "l"(sp));
                    const bool ok = (s0 - base) >= (unsigned)t && (s1 - base) >= (unsigned)t
                                 && (s2 - base) >= (unsigned)t && (s3 - base) >= (unsigned)t;
                    if (__all_sync(0xffffffffu, ok)) break;
                }
                __threadfence();
            }
            __syncthreads();
            if (tid < 512)
                ((uint4*)hq)[tid] = ((const uint4*)g_hq[(t - 1) & 1])[tid];
            __syncthreads();

            int acc[4] = {0, 0, 0, 0};
            // smem-resident chunks
            DOCHUNK_SM(0); DOCHUNK_SM(1); DOCHUNK_SM(2);
            DOCHUNK_SM(3); DOCHUNK_SM(4); DOCHUNK_SM(5);
            // streamed chunks, triple-buffered (distance ~3 chunks)
            DOCHUNK_SB(6,  sb0); LDSB(sb0, 9);
            DOCHUNK_SB(7,  sb1); LDSB(sb1, 10);
            DOCHUNK_SB(8,  sb2); LDSB(sb2, 11);
            DOCHUNK_SB(9,  sb0); LDSB(sb0, 12);
            DOCHUNK_SB(10, sb1); LDSB(sb1, 13);
            DOCHUNK_SB(11, sb2); LDSB(sb2, 14);
            DOCHUNK_SB(12, sb0); LDSB(sb0, 15);
            DOCHUNK_SB(13, sb1);
            DOCHUNK_SB(14, sb2);
            DOCHUNK_SB(15, sb0);

            // reduce 4 rows per warp
            #pragma unroll
            for (int rr = 0; rr < 4; ++rr) {
                float a = __int2float_rn(acc[rr]);
                #pragma unroll
                for (int o = 16; o > 0; o >>= 1)
                    a += __shfl_down_sync(0xffffffffu, a, o);
                if (lane == 0) {
                    const int rloc = wid * 4 + rr;
                    const int gate = rloc >> 5, jj = rloc & 31;
                    gsm[gate][jj] = a * (g_scale[gate * H + j0 + jj] * (1.0f / 32767.0f));
                }
            }
        }
        __syncthreads();

        if (tid < JPB) {
            const int   j  = j0 + tid;
            const float xt = x[t];
            float v[4];
            #pragma unroll
            for (int g = 0; g < 4; ++g) {
                const int row = g * H + j;
                const float dot = (t > 0) ? gsm[g][tid] : 0.0f;
                v[g] = fmaf(w_ih[row], xt, b_ih[row] + b_hh[row]) + dot;
            }
            const float ig = 1.0f / (1.0f + expf(-v[0]));
            const float fg = 1.0f / (1.0f + expf(-v[1]));
            const float gg = tanhf(v[2]);
            const float og = 1.0f / (1.0f + expf(-v[3]));
            const float c  = fg * c_s[tid] + ig * gg;
            c_s[tid] = c;
            const float h = og * tanhf(c);
            hnew[tid] = h;
            if (t == SEQ - 1) g_h[j] = h;
        }
        __syncthreads();
        if (tid < JPB / 2) {
            const int q0 = __float2int_rn(hnew[2 * tid]     * 32767.0f);
            const int q1 = __float2int_rn(hnew[2 * tid + 1] * 32767.0f);
            g_hq[t & 1][j0 / 2 + tid] = __byte_perm((unsigned)q0, (unsigned)q1, 0x5410);
        }
        __syncthreads();
        if (tid == 0) {
            __threadfence();
            *(volatile unsigned*)&g_stamp[blockIdx.x] = base + (unsigned)(t + 1);
        }
    }

    // final sync: all blocks published h_last
    if (wid == 0) {
        const unsigned* sp = g_stamp + lane * 4;
        for (;;) {
            unsigned s0, s1, s2, s3;
            asm volatile("ld.volatile.global.v4.u32 {%0,%1,%2,%3}, [%4];"
                         : "=r"(s0), "=r"(s1), "=r"(s2), "=r"(s3) : "l"(sp));
            const bool ok = (s0 - base) >= SEQ && (s1 - base) >= SEQ
                         && (s2 - base) >= SEQ && (s3 - base) >= SEQ;
            if (__all_sync(0xffffffffu, ok)) break;
        }
        __threadfence();
    }
    __syncthreads();

    // dense epilogue: block b computes out[b] (NBLK == OUT)
    {
        const float* hw = g_h;
        const float* wr = dense_w + (size_t)blockIdx.x * H;
        float acc = 0.0f;
        #pragma unroll
        for (int k = tid; k < H; k += NTHR)
            acc += wr[k] * hw[k];
        #pragma unroll
        for (int o = 16; o > 0; o >>= 1)
            acc += __shfl_down_sync(0xffffffffu, acc, o);
        if (lane == 0) red[wid] = acc;
        __syncthreads();
        if (tid == 0) {
            float s = 0.0f;
            #pragma unroll
            for (int w = 0; w < NTHR / 32; ++w) s += red[w];
            out[blockIdx.x] = s + dense_b[blockIdx.x];
        }
    }
}

extern "C" void kernel_launch(void* const* d_in, const int* in_sizes, int n_in,
                              void* d_out, int out_size) {
    const float* x       = (const float*)d_in[0];
    const float* w_ih    = (const float*)d_in[1];
    const float* w_hh    = (const float*)d_in[2];
    const float* b_ih    = (const float*)d_in[3];
    const float* b_hh    = (const float*)d_in[4];
    const float* dense_w = (const float*)d_in[5];
    const float* dense_b = (const float*)d_in[6];

    cudaFuncSetAttribute(lstm_persistent_kernel,
                         cudaFuncAttributeMaxDynamicSharedMemorySize, SMEM_W);
    quant_kernel<<<ROWS, 256>>>(w_hh);
    lstm_persistent_kernel<<<NBLK, NTHR, SMEM_W>>>(x, w_ih, b_ih, b_hh,
                                                   dense_w, dense_b, (float*)d_out);
}

// round 11
// speedup vs baseline: 1.1426x; 1.1382x over previous
#include <cuda_runtime.h>
#include <math.h>

#define SEQ   40
#define H     4096
#define OUT   128
#define NBLK  128
#define NTHR  1024
#define JPB   32                  // hidden indices per block (= warps per block)
#define RPB   128                 // rows per block (32 j x 4 gates)
#define ROWS  (4 * H)
#define CH_B  32768               // bytes per chunk (128 rows x 256 cols)
#define NCHUNK 16
#define SCH   6                   // chunks 0..5 resident in smem (192 KB)
#define BLOCK_WQ (RPB * H)        // 512 KB s8 weights per block
#define SMEM_W (SCH * CH_B)

// ---- persistent device state ----
__device__ float    g_h[H];                                      // fp32 h_last for dense
__device__ unsigned g_hq[2][H / 2];                              // ping-pong s16 h (u16[H])
__device__ float    g_scale[ROWS];                               // per-row dequant scale
__device__ __align__(256) unsigned char g_wq[(size_t)NBLK * BLOCK_WQ]; // 67MB s8
__device__ __align__(16) unsigned g_stamp[NBLK];                 // per-block step stamps

// ---------------- quant; layout [B][chunk][rloc=(j&31)*4+gate][256B] ----------------
__global__ __launch_bounds__(256) void quant_kernel(const float* __restrict__ w_hh) {
    __shared__ float wmax[8];
    const int r    = blockIdx.x;             // gate row (gate*H + j)
    const int tid  = threadIdx.x;
    const int lane = tid & 31, wrp = tid >> 5;

    const float4* rp = (const float4*)(w_hh + (size_t)r * H) + tid * 4;
    const float4 vs[4] = {__ldg(rp), __ldg(rp + 1), __ldg(rp + 2), __ldg(rp + 3)};

    float m = 0.0f;
    #pragma unroll
    for (int q = 0; q < 4; ++q)
        m = fmaxf(m, fmaxf(fmaxf(fabsf(vs[q].x), fabsf(vs[q].y)),
                           fmaxf(fabsf(vs[q].z), fabsf(vs[q].w))));
    #pragma unroll
    for (int o = 16; o > 0; o >>= 1) m = fmaxf(m, __shfl_xor_sync(0xffffffffu, m, o));
    if (lane == 0) wmax[wrp] = m;
    __syncthreads();
    float mx = wmax[0];
    #pragma unroll
    for (int w = 1; w < 8; ++w) mx = fmaxf(mx, wmax[w]);
    if (tid == 0) g_scale[r] = mx * (1.0f / 127.0f);
    const float inv = (mx > 0.0f) ? 127.0f / mx : 0.0f;

    unsigned b[16];
    #pragma unroll
    for (int q = 0; q < 4; ++q) {
        b[4 * q + 0] = __float_as_uint(fmaf(vs[q].x, inv, 8388736.0f));
        b[4 * q + 1] = __float_as_uint(fmaf(vs[q].y, inv, 8388736.0f));
        b[4 * q + 2] = __float_as_uint(fmaf(vs[q].z, inv, 8388736.0f));
        b[4 * q + 3] = __float_as_uint(fmaf(vs[q].w, inv, 8388736.0f));
    }
    uint4 o;
    #pragma unroll
    for (int q = 0; q < 4; ++q) {
        unsigned t0 = __byte_perm(b[4 * q + 0], b[4 * q + 1], 0x0040);
        unsigned t1 = __byte_perm(b[4 * q + 2], b[4 * q + 3], 0x0040);
        ((unsigned*)&o)[q] = __byte_perm(t0, t1, 0x5410) ^ 0x80808080u;
    }
    const int j = r & (H - 1), gate = r >> 12;
    const int B = j >> 5;
    const int rloc = (j & 31) * 4 + gate;            // warp-owns-j layout
    *(uint4*)(g_wq + (size_t)B * BLOCK_WQ + (size_t)(tid >> 4) * CH_B
              + rloc * 256 + (tid & 15) * 16) = o;
}

#define DOROW(rr, WV) do {                                                \
    acc[rr] = __dp2a_lo((int)hv.x, (int)(WV).x, acc[rr]);                 \
    acc[rr] = __dp2a_hi((int)hv.y, (int)(WV).x, acc[rr]);                 \
    acc[rr] = __dp2a_lo((int)hv.z, (int)(WV).y, acc[rr]);                 \
    acc[rr] = __dp2a_hi((int)hv.w, (int)(WV).y, acc[rr]);                 \
} while (0)

#define DOCHUNK_SM(cc) do {                                               \
    const uint4 hv = *(const uint4*)(hq + (cc) * 128 + 4 * lane);         \
    const unsigned char* _c = wsm + (size_t)(cc) * CH_B + wid * 1024 + lane * 8; \
    DOROW(0, *(const uint2*)(_c));                                        \
    DOROW(1, *(const uint2*)(_c + 256));                                  \
    DOROW(2, *(const uint2*)(_c + 512));                                  \
    DOROW(3, *(const uint2*)(_c + 768));                                  \
} while (0)

#define DOCHUNK_SB(cc, SB) do {                                           \
    const uint4 hv = *(const uint4*)(hq + (cc) * 128 + 4 * lane);         \
    DOROW(0, SB[0]); DOROW(1, SB[1]); DOROW(2, SB[2]); DOROW(3, SB[3]);   \
} while (0)

#define LDSB(dst, cc) do {                                                \
    const unsigned char* _p = wsrc + (size_t)(cc) * CH_B + wid * 1024 + lane * 8; \
    dst[0] = __ldg((const uint2*)(_p));                                   \
    dst[1] = __ldg((const uint2*)(_p + 256));                             \
    dst[2] = __ldg((const uint2*)(_p + 512));                             \
    dst[3] = __ldg((const uint2*)(_p + 768)); } while (0)

__device__ __forceinline__ float sigf(float v) { return 1.0f / (1.0f + __expf(-v)); }

// ---------------- persistent LSTM kernel ----------------
__global__ __launch_bounds__(NTHR, 1)
void lstm_persistent_kernel(const float* __restrict__ x,
                            const float* __restrict__ w_ih,
                            const float* __restrict__ b_ih,
                            const float* __restrict__ b_hh,
                            const float* __restrict__ dense_w,
                            const float* __restrict__ dense_b,
                            float* __restrict__ out) {
    extern __shared__ unsigned char wsm[];       // 192 KB resident weights (chunks 0..5)
    __shared__ unsigned hq[H / 2];               // 8 KB packed h_{t-1}
    __shared__ float xs[SEQ];                    // all timestep inputs
    __shared__ float red[NTHR / 32];

    const int tid  = threadIdx.x;
    const int lane = tid & 31;
    const int wid  = tid >> 5;                   // warp owns j = j0 + wid (rows 4wid..4wid+3)
    const int j0   = blockIdx.x * JPB;
    const int j    = j0 + wid;
    const unsigned char* wsrc = g_wq + (size_t)blockIdx.x * BLOCK_WQ;

    // hoisted per-j constants (replicated across lanes; tiny)
    float wih[4], bsum[4], scl[4];
    #pragma unroll
    for (int g = 0; g < 4; ++g) {
        const int row = g * H + j;
        wih[g]  = __ldg(w_ih + row);
        bsum[g] = __ldg(b_ih + row) + __ldg(b_hh + row);
        scl[g]  = __ldg(g_scale + row) * (1.0f / 32767.0f);
    }
    if (tid < SEQ) xs[tid] = x[tid];

    // copy smem-resident chunks 0..5
    {
        const uint4* gsrc = (const uint4*)wsrc;
        uint4* d = (uint4*)wsm;
        #pragma unroll
        for (int i = 0; i < SMEM_W / 16 / NTHR; ++i)
            d[tid + i * NTHR] = __ldg(gsrc + tid + i * NTHR);
    }

    const unsigned base = *(volatile unsigned*)&g_stamp[blockIdx.x];
    float c_reg = 0.0f;                          // cell state carried in lane-0 register

    for (int t = 0; t < SEQ; ++t) {
        float dot[4] = {0.0f, 0.0f, 0.0f, 0.0f};
        if (t > 0) {
            // prefetch first three streamed chunks before the poll
            uint2 sb0[4], sb1[4], sb2[4];
            LDSB(sb0, 6); LDSB(sb1, 7); LDSB(sb2, 8);

            if (wid == 0) {                      // warp 0 polls all 128 stamps
                const unsigned* sp = g_stamp + lane * 4;
                for (;;) {
                    unsigned s0, s1, s2, s3;
                    asm volatile("ld.volatile.global.v4.u32 {%0,%1,%2,%3}, [%4];"
                                 : "=r"(s0), "=r"(s1), "=r"(s2), "=r"(s3) : "l"(sp));
                    const bool ok = (s0 - base) >= (unsigned)t && (s1 - base) >= (unsigned)t
                                 && (s2 - base) >= (unsigned)t && (s3 - base) >= (unsigned)t;
                    if (__all_sync(0xffffffffu, ok)) break;
                }
                __threadfence();
            }
            __syncthreads();                     // bar 1: h(t-1) globally ready
            if (tid < 512)
                ((uint4*)hq)[tid] = ((const uint4*)g_hq[(t - 1) & 1])[tid];
            __syncthreads();                     // bar 2: hq staged

            int acc[4] = {0, 0, 0, 0};
            DOCHUNK_SM(0); DOCHUNK_SM(1); DOCHUNK_SM(2);
            DOCHUNK_SM(3); DOCHUNK_SM(4); DOCHUNK_SM(5);
            DOCHUNK_SB(6,  sb0); LDSB(sb0, 9);
            DOCHUNK_SB(7,  sb1); LDSB(sb1, 10);
            DOCHUNK_SB(8,  sb2); LDSB(sb2, 11);
            DOCHUNK_SB(9,  sb0); LDSB(sb0, 12);
            DOCHUNK_SB(10, sb1); LDSB(sb1, 13);
            DOCHUNK_SB(11, sb2); LDSB(sb2, 14);
            DOCHUNK_SB(12, sb0); LDSB(sb0, 15);
            DOCHUNK_SB(13, sb1);
            DOCHUNK_SB(14, sb2);
            DOCHUNK_SB(15, sb0);

            // single-instruction warp reductions (exact s32)
            #pragma unroll
            for (int rr = 0; rr < 4; ++rr)
                dot[rr] = __int2float_rn(__reduce_add_sync(0xffffffffu, acc[rr])) * scl[rr];
        }

        // in-warp elementwise (lane 0), register-carried c
        if (lane == 0) {
            const float xt = xs[t];
            const float vi = fmaf(wih[0], xt, bsum[0]) + dot[0];
            const float vf = fmaf(wih[1], xt, bsum[1]) + dot[1];
            const float vg = fmaf(wih[2], xt, bsum[2]) + dot[2];
            const float vo = fmaf(wih[3], xt, bsum[3]) + dot[3];
            const float c  = sigf(vf) * c_reg + sigf(vi) * tanhf(vg);
            c_reg = c;
            const float h = sigf(vo) * tanhf(c);
            ((unsigned short*)g_hq[t & 1])[j] =
                (unsigned short)(short)__float2int_rn(h * 32767.0f);
            if (t == SEQ - 1) g_h[j] = h;
            asm volatile("membar.gl;" ::: "memory");   // publish h before bar+stamp
        }
        __syncthreads();                         // bar 3: all 32 h stored+fenced
        if (tid == 0)
            *(volatile unsigned*)&g_stamp[blockIdx.x] = base + (unsigned)(t + 1);
    }

    // final sync: all blocks published h_last
    if (wid == 0) {
        const unsigned* sp = g_stamp + lane * 4;
        for (;;) {
            unsigned s0, s1, s2, s3;
            asm volatile("ld.volatile.global.v4.u32 {%0,%1,%2,%3}, [%4];"
                         : "=r"(s0), "=r"(s1), "=r"(s2), "=r"(s3) : "l"(sp));
            const bool ok = (s0 - base) >= SEQ && (s1 - base) >= SEQ
                         && (s2 - base) >= SEQ && (s3 - base) >= SEQ;
            if (__all_sync(0xffffffffu, ok)) break;
        }
        __threadfence();
    }
    __syncthreads();

    // dense epilogue: block b computes out[b] (NBLK == OUT)
    {
        const float* hw = g_h;
        const float* wr = dense_w + (size_t)blockIdx.x * H;
        float acc = 0.0f;
        #pragma unroll
        for (int k = tid; k < H; k += NTHR)
            acc += wr[k] * hw[k];
        #pragma unroll
        for (int o = 16; o > 0; o >>= 1)
            acc += __shfl_down_sync(0xffffffffu, acc, o);
        if (lane == 0) red[wid] = acc;
        __syncthreads();
        if (tid == 0) {
            float s = 0.0f;
            #pragma unroll
            for (int w = 0; w < NTHR / 32; ++w) s += red[w];
            out[blockIdx.x] = s + dense_b[blockIdx.x];
        }
    }
}

extern "C" void kernel_launch(void* const* d_in, const int* in_sizes, int n_in,
                              void* d_out, int out_size) {
    const float* x       = (const float*)d_in[0];
    const float* w_ih    = (const float*)d_in[1];
    const float* w_hh    = (const float*)d_in[2];
    const float* b_ih    = (const float*)d_in[3];
    const float* b_hh    = (const float*)d_in[4];
    const float* dense_w = (const float*)d_in[5];
    const float* dense_b = (const float*)d_in[6];

    cudaFuncSetAttribute(lstm_persistent_kernel,
                         cudaFuncAttributeMaxDynamicSharedMemorySize, SMEM_W);
    quant_kernel<<<ROWS, 256>>>(w_hh);
    lstm_persistent_kernel<<<NBLK, NTHR, SMEM_W>>>(x, w_ih, b_ih, b_hh,
                                                   dense_w, dense_b, (float*)d_out);
}

// round 12
// speedup vs baseline: 1.7224x; 1.5074x over previous
#include <cuda_runtime.h>
#include <math.h>

#define SEQ   40
#define H     4096
#define OUT   128
#define NBLK  128
#define NTHR  1024
#define JPB   32                  // hidden indices per block (= warps per block)
#define RPB   128                 // rows per block (32 j x 4 gates)
#define ROWS  (4 * H)
#define CH_B  32768               // bytes per chunk (128 rows x 256 cols)
#define NCHUNK 16
#define SCH   6                   // chunks 0..5 resident in smem (192 KB)
#define BLOCK_WQ (RPB * H)        // 512 KB s8 weights per block
#define SMEM_W (SCH * CH_B)

// ---- persistent device state ----
__device__ float    g_h[H];                                      // fp32 h_last for dense
__device__ unsigned g_hq[2][H / 2];                              // ping-pong s16 h (u16[H])
__device__ float    g_scale[ROWS];                               // per-row dequant scale
__device__ __align__(256) unsigned char g_wq[(size_t)NBLK * BLOCK_WQ]; // 67MB s8
__device__ __align__(16) unsigned g_stamp[NBLK];                 // per-block step stamps

// ---------------- quant; paired-row layout ----------------
// [B][chunk][warp=j&31][pair=gate>>1][lane 16B: {r2p.c8l..+3, r2p.c+4..+7, r2p+1.c.., r2p+1.c..}]
__global__ __launch_bounds__(256) void quant_kernel(const float* __restrict__ w_hh) {
    __shared__ float wmax[8];
    const int r    = blockIdx.x;             // gate row (gate*H + j)
    const int tid  = threadIdx.x;
    const int lane = tid & 31, wrp = tid >> 5;

    const float4* rp = (const float4*)(w_hh + (size_t)r * H) + tid * 4;
    const float4 vs[4] = {__ldg(rp), __ldg(rp + 1), __ldg(rp + 2), __ldg(rp + 3)};

    float m = 0.0f;
    #pragma unroll
    for (int q = 0; q < 4; ++q)
        m = fmaxf(m, fmaxf(fmaxf(fabsf(vs[q].x), fabsf(vs[q].y)),
                           fmaxf(fabsf(vs[q].z), fabsf(vs[q].w))));
    #pragma unroll
    for (int o = 16; o > 0; o >>= 1) m = fmaxf(m, __shfl_xor_sync(0xffffffffu, m, o));
    if (lane == 0) wmax[wrp] = m;
    __syncthreads();
    float mx = wmax[0];
    #pragma unroll
    for (int w = 1; w < 8; ++w) mx = fmaxf(mx, wmax[w]);
    if (tid == 0) g_scale[r] = mx * (1.0f / 127.0f);
    const float inv = (mx > 0.0f) ? 127.0f / mx : 0.0f;

    unsigned b[16];
    #pragma unroll
    for (int q = 0; q < 4; ++q) {
        b[4 * q + 0] = __float_as_uint(fmaf(vs[q].x, inv, 8388736.0f));
        b[4 * q + 1] = __float_as_uint(fmaf(vs[q].y, inv, 8388736.0f));
        b[4 * q + 2] = __float_as_uint(fmaf(vs[q].z, inv, 8388736.0f));
        b[4 * q + 3] = __float_as_uint(fmaf(vs[q].w, inv, 8388736.0f));
    }
    uint4 o;
    #pragma unroll
    for (int q = 0; q < 4; ++q) {
        unsigned t0 = __byte_perm(b[4 * q + 0], b[4 * q + 1], 0x0040);
        unsigned t1 = __byte_perm(b[4 * q + 2], b[4 * q + 3], 0x0040);
        ((unsigned*)&o)[q] = __byte_perm(t0, t1, 0x5410) ^ 0x80808080u;
    }
    const int j = r & (H - 1), gate = r >> 12;
    const int B = j >> 5;
    const int wid_ = j & 31;
    const int p = gate >> 1, rp_ = gate & 1;
    const int chunk = tid >> 4;
    const int lpos = (tid & 15) * 2;         // first of two dest lanes
    unsigned char* dst = g_wq + (size_t)B * BLOCK_WQ + (size_t)chunk * CH_B
                       + wid_ * 1024 + p * 512 + rp_ * 8;
    *(uint2*)(dst + lpos * 16)       = make_uint2(o.x, o.y);   // cols 16T..16T+7
    *(uint2*)(dst + (lpos + 1) * 16) = make_uint2(o.z, o.w);   // cols 16T+8..+15
}

// pair uint4 Q holds rows (2p, 2p+1): Q.x/Q.y = row 2p, Q.z/Q.w = row 2p+1
#define DOPAIR(p, Q) do {                                                 \
    acc[2*(p)]   = __dp2a_lo((int)hv.x, (int)(Q).x, acc[2*(p)]);          \
    acc[2*(p)]   = __dp2a_hi((int)hv.y, (int)(Q).x, acc[2*(p)]);          \
    acc[2*(p)]   = __dp2a_lo((int)hv.z, (int)(Q).y, acc[2*(p)]);          \
    acc[2*(p)]   = __dp2a_hi((int)hv.w, (int)(Q).y, acc[2*(p)]);          \
    acc[2*(p)+1] = __dp2a_lo((int)hv.x, (int)(Q).z, acc[2*(p)+1]);        \
    acc[2*(p)+1] = __dp2a_hi((int)hv.y, (int)(Q).z, acc[2*(p)+1]);        \
    acc[2*(p)+1] = __dp2a_lo((int)hv.z, (int)(Q).w, acc[2*(p)+1]);        \
    acc[2*(p)+1] = __dp2a_hi((int)hv.w, (int)(Q).w, acc[2*(p)+1]);        \
} while (0)

#define DOCHUNK_SM(cc) do {                                               \
    const uint4 hv = *(const uint4*)(hq + (cc) * 128 + 4 * lane);         \
    const unsigned char* _c = wsm + (size_t)(cc) * CH_B + wid * 1024 + lane * 16; \
    const uint4 q0 = *(const uint4*)(_c);                                 \
    const uint4 q1 = *(const uint4*)(_c + 512);                           \
    DOPAIR(0, q0); DOPAIR(1, q1);                                         \
} while (0)

#define DOCHUNK_SB(cc, SB) do {                                           \
    const uint4 hv = *(const uint4*)(hq + (cc) * 128 + 4 * lane);         \
    DOPAIR(0, SB[0]); DOPAIR(1, SB[1]);                                   \
} while (0)

#define LDSB(dst, cc) do {                                                \
    const unsigned char* _p = wsrc + (size_t)(cc) * CH_B + wid * 1024 + lane * 16; \
    dst[0] = __ldg((const uint4*)(_p));                                   \
    dst[1] = __ldg((const uint4*)(_p + 512)); } while (0)

__device__ __forceinline__ float sigf(float v) { return 1.0f / (1.0f + __expf(-v)); }

// ---------------- persistent LSTM kernel ----------------
__global__ __launch_bounds__(NTHR, 1)
void lstm_persistent_kernel(const float* __restrict__ x,
                            const float* __restrict__ w_ih,
                            const float* __restrict__ b_ih,
                            const float* __restrict__ b_hh,
                            const float* __restrict__ dense_w,
                            const float* __restrict__ dense_b,
                            float* __restrict__ out) {
    extern __shared__ unsigned char wsm[];       // 192 KB resident weights (chunks 0..5)
    __shared__ unsigned hq[H / 2];               // 8 KB packed h_{t-1}
    __shared__ float xs[SEQ];
    __shared__ float red[NTHR / 32];

    const int tid  = threadIdx.x;
    const int lane = tid & 31;
    const int wid  = tid >> 5;                   // warp owns j = j0 + wid (gates 0..3)
    const int j0   = blockIdx.x * JPB;
    const int j    = j0 + wid;
    const unsigned char* wsrc = g_wq + (size_t)blockIdx.x * BLOCK_WQ;

    // per-lane gate constants: lane g (g<4) holds gate g's scalars
    const int grow = (lane & 3) * H + j;
    const float wih_l  = __ldg(w_ih + grow);
    const float bsum_l = __ldg(b_ih + grow) + __ldg(b_hh + grow);
    const float scl_l  = __ldg(g_scale + grow) * (1.0f / 32767.0f);
    if (tid < SEQ) xs[tid] = x[tid];

    // copy smem-resident chunks 0..5
    {
        const uint4* gsrc = (const uint4*)wsrc;
        uint4* d = (uint4*)wsm;
        #pragma unroll
        for (int i = 0; i < SMEM_W / 16 / NTHR; ++i)
            d[tid + i * NTHR] = __ldg(gsrc + tid + i * NTHR);
    }

    const unsigned base = *(volatile unsigned*)&g_stamp[blockIdx.x];
    float c_reg = 0.0f;

    for (int t = 0; t < SEQ; ++t) {
        int rsel = 0;
        if (t > 0) {
            // prefetch first four streamed chunks (independent of h)
            uint4 sb0[2], sb1[2], sb2[2], sb3[2];
            LDSB(sb0, 6); LDSB(sb1, 7); LDSB(sb2, 8); LDSB(sb3, 9);

            // fine-grained staging: thread tid waits only for ITS piece's producer
            if (tid < 512) {
                const unsigned* sp = &g_stamp[tid >> 2];
                unsigned s;
                do {
                    asm volatile("ld.acquire.gpu.global.u32 %0, [%1];"
                                 : "=r"(s) : "l"(sp));
                } while (s - base < (unsigned)t);
                ((uint4*)hq)[tid] = ((const uint4*)g_hq[(t - 1) & 1])[tid];
            }
            __syncthreads();                     // bar A: hq fully staged

            int acc[4] = {0, 0, 0, 0};
            DOCHUNK_SM(0); DOCHUNK_SM(1); DOCHUNK_SM(2);
            DOCHUNK_SM(3); DOCHUNK_SM(4); DOCHUNK_SM(5);
            DOCHUNK_SB(6,  sb0); LDSB(sb0, 10);
            DOCHUNK_SB(7,  sb1); LDSB(sb1, 11);
            DOCHUNK_SB(8,  sb2); LDSB(sb2, 12);
            DOCHUNK_SB(9,  sb3); LDSB(sb3, 13);
            DOCHUNK_SB(10, sb0); LDSB(sb0, 14);
            DOCHUNK_SB(11, sb1); LDSB(sb1, 15);
            DOCHUNK_SB(12, sb2);
            DOCHUNK_SB(13, sb3);
            DOCHUNK_SB(14, sb0);
            DOCHUNK_SB(15, sb1);

            const int r0 = __reduce_add_sync(0xffffffffu, acc[0]);
            const int r1 = __reduce_add_sync(0xffffffffu, acc[1]);
            const int r2 = __reduce_add_sync(0xffffffffu, acc[2]);
            const int r3 = __reduce_add_sync(0xffffffffu, acc[3]);
            rsel = (lane == 1) ? r1 : (lane == 2) ? r2 : (lane == 3) ? r3 : r0;
        }

        // gate-parallel tail: lanes 0..3 evaluate their gate's activation
        {
            const float xt = xs[t];
            const float v  = fmaf(wih_l, xt, bsum_l) + __int2float_rn(rsel) * scl_l;
            const float act = (lane == 2) ? tanhf(v) : sigf(v);
            const float a1 = __shfl_sync(0xffffffffu, act, 1);
            const float a2 = __shfl_sync(0xffffffffu, act, 2);
            const float a3 = __shfl_sync(0xffffffffu, act, 3);
            if (lane == 0) {
                const float c = a1 * c_reg + act * a2;   // sig(f)*c + sig(i)*tanh(g)
                c_reg = c;
                const float h = a3 * tanhf(c);
                ((unsigned short*)g_hq[t & 1])[j] =
                    (unsigned short)(short)__float2int_rn(h * 32767.0f);
                if (t == SEQ - 1) g_h[j] = h;
                asm volatile("membar.gl;" ::: "memory");
            }
        }
        __syncthreads();                         // bar B: all h stored+fenced
        if (tid == 0)
            *(volatile unsigned*)&g_stamp[blockIdx.x] = base + (unsigned)(t + 1);
    }

    // final sync: all blocks published h_last
    if (wid == 0) {
        const unsigned* sp = g_stamp + lane * 4;
        for (;;) {
            unsigned s0, s1, s2, s3;
            asm volatile("ld.volatile.global.v4.u32 {%0,%1,%2,%3}, [%4];"
                         : "=r"(s0), "=r"(s1), "=r"(s2), "=r"(s3) : "l"(sp));
            const bool ok = (s0 - base) >= SEQ && (s1 - base) >= SEQ
                         && (s2 - base) >= SEQ && (s3 - base) >= SEQ;
            if (__all_sync(0xffffffffu, ok)) break;
        }
        __threadfence();
    }
    __syncthreads();

    // dense epilogue: block b computes out[b] (NBLK == OUT)
    {
        const float* hw = g_h;
        const float* wr = dense_w + (size_t)blockIdx.x * H;
        float acc = 0.0f;
        #pragma unroll
        for (int k = tid; k < H; k += NTHR)
            acc += wr[k] * hw[k];
        #pragma unroll
        for (int o = 16; o > 0; o >>= 1)
            acc += __shfl_down_sync(0xffffffffu, acc, o);
        if (lane == 0) red[wid] = acc;
        __syncthreads();
        if (tid == 0) {
            float s = 0.0f;
            #pragma unroll
            for (int w = 0; w < NTHR / 32; ++w) s += red[w];
            out[blockIdx.x] = s + dense_b[blockIdx.x];
        }
    }
}

extern "C" void kernel_launch(void* const* d_in, const int* in_sizes, int n_in,
                              void* d_out, int out_size) {
    const float* x       = (const float*)d_in[0];
    const float* w_ih    = (const float*)d_in[1];
    const float* w_hh    = (const float*)d_in[2];
    const float* b_ih    = (const float*)d_in[3];
    const float* b_hh    = (const float*)d_in[4];
    const float* dense_w = (const float*)d_in[5];
    const float* dense_b = (const float*)d_in[6];

    cudaFuncSetAttribute(lstm_persistent_kernel,
                         cudaFuncAttributeMaxDynamicSharedMemorySize, SMEM_W);
    quant_kernel<<<ROWS, 256>>>(w_hh);
    lstm_persistent_kernel<<<NBLK, NTHR, SMEM_W>>>(x, w_ih, b_ih, b_hh,
                                                   dense_w, dense_b, (float*)d_out);
}